// round 10
// baseline (speedup 1.0000x reference)
#include <cuda_runtime.h>
#include <math.h>
#include <stdint.h>

// ---------------- problem constants ----------------
#define kB    16
#define kH    64
#define kW    64
#define kC    192
#define kHD   32
#define kNH   6
#define kP    8
#define kSH   4            // SHIFT
#define kNW   64           // (H/P)*(W/P)
#define kPP   64           // P*P
#define kTOK  (kB*kH*kW)   // 65536

// ---------------- device scratch (no allocation allowed) ----------------
__device__ float g_hwin[(size_t)kTOK * kC];
__device__ float g_qkv [(size_t)kTOK * 3 * kC];
__device__ float g_attn[(size_t)kTOK * kC];
__device__ float g_x1  [(size_t)kTOK * kC];
__device__ float g_h2n [(size_t)kTOK * kC];
__device__ float g_mid [(size_t)kTOK * 4 * kC];
__device__ float g_btab[kNH * kPP * kPP];

// ---------------- PTX helpers (sm_80-level only) ----------------
__device__ __forceinline__ void mma_tf32(float* d,
                                         uint32_t a0, uint32_t a1, uint32_t a2, uint32_t a3,
                                         uint32_t b0, uint32_t b1) {
    asm volatile(
        "mma.sync.aligned.m16n8k8.row.col.f32.tf32.tf32.f32 "
        "{%0,%1,%2,%3}, {%4,%5,%6,%7}, {%8,%9}, {%0,%1,%2,%3};"
        : "+f"(d[0]), "+f"(d[1]), "+f"(d[2]), "+f"(d[3])
        : "r"(a0), "r"(a1), "r"(a2), "r"(a3), "r"(b0), "r"(b1));
}
__device__ __forceinline__ uint32_t s2u(const void* p) {
    return (uint32_t)__cvta_generic_to_shared(p);
}
__device__ __forceinline__ void cpa16(uint32_t dst, const void* src) {
    asm volatile("cp.async.cg.shared.global [%0], [%1], 16;" :: "r"(dst), "l"(src));
}
__device__ __forceinline__ void cpa_commit() {
    asm volatile("cp.async.commit_group;" ::: "memory");
}
template<int N> __device__ __forceinline__ void cpa_wait() {
    asm volatile("cp.async.wait_group %0;" :: "n"(N) : "memory");
}

// ---------------- relative position bias table ----------------
__global__ void btab_kernel(const float* __restrict__ rel) {
    int idx = blockIdx.x * 256 + threadIdx.x;
    if (idx >= kNH * kPP * kPP) return;
    int h = idx >> 12;
    int r = idx & 4095;
    int p = r >> 6, q = r & 63;
    int dy = (p >> 3) - (q >> 3) + (kP - 1);
    int dx = (p & 7)  - (q & 7)  + (kP - 1);
    g_btab[idx] = rel[h * (2*kP-1)*(2*kP-1) + dy * (2*kP-1) + dx];
}

// ---------------- LayerNorm kernels ----------------
__global__ void ln1_kernel(const float* __restrict__ x,
                           const float* __restrict__ g,
                           const float* __restrict__ bt) {
    int t = blockIdx.x;
    int c = threadIdx.x;
    int b = t >> 12;
    int ij = t & 4095;
    int i = ij >> 6, j = ij & 63;
    int si = (i + kSH) & 63, sj = (j + kSH) & 63;
    float v = x[((size_t)(((b << 6) + si) << 6) + sj) * kC + c];

    __shared__ float red1[6], red2[6];
    int wid = c >> 5, lane = c & 31;
    float s = v;
    #pragma unroll
    for (int o = 16; o; o >>= 1) s += __shfl_xor_sync(0xffffffffu, s, o);
    if (lane == 0) red1[wid] = s;
    __syncthreads();
    float mean = (red1[0]+red1[1]+red1[2]+red1[3]+red1[4]+red1[5]) * (1.0f/kC);
    float d = v - mean;
    float q = d * d;
    #pragma unroll
    for (int o = 16; o; o >>= 1) q += __shfl_xor_sync(0xffffffffu, q, o);
    if (lane == 0) red2[wid] = q;
    __syncthreads();
    float var = (red2[0]+red2[1]+red2[2]+red2[3]+red2[4]+red2[5]) * (1.0f/kC);
    float out = d * rsqrtf(var + 1e-5f) * g[c] + bt[c];

    int wi = i >> 3, pi = i & 7, wj = j >> 3, pj = j & 7;
    int n  = (wi << 3) + wj;
    int p  = (pi << 3) + pj;
    size_t row = (size_t)((b << 6) + n) * 64 + p;
    g_hwin[row * kC + c] = out;
}

__global__ void ln2_kernel(const float* __restrict__ g,
                           const float* __restrict__ bt) {
    int t = blockIdx.x;
    int c = threadIdx.x;
    float v = g_x1[(size_t)t * kC + c];

    __shared__ float red1[6], red2[6];
    int wid = c >> 5, lane = c & 31;
    float s = v;
    #pragma unroll
    for (int o = 16; o; o >>= 1) s += __shfl_xor_sync(0xffffffffu, s, o);
    if (lane == 0) red1[wid] = s;
    __syncthreads();
    float mean = (red1[0]+red1[1]+red1[2]+red1[3]+red1[4]+red1[5]) * (1.0f/kC);
    float d = v - mean;
    float q = d * d;
    #pragma unroll
    for (int o = 16; o; o >>= 1) q += __shfl_xor_sync(0xffffffffu, q, o);
    if (lane == 0) red2[wid] = q;
    __syncthreads();
    float var = (red2[0]+red2[1]+red2[2]+red2[3]+red2[4]+red2[5]) * (1.0f/kC);
    g_h2n[(size_t)t * kC + c] = d * rsqrtf(var + 1e-5f) * g[c] + bt[c];
}

// ---------------- window-reverse + roll-back row mapping ----------------
__device__ __forceinline__ int map_row(int r) {
    int b   = r >> 12;
    int rem = r & 4095;
    int n = rem >> 6, p = rem & 63;
    int wi = n >> 3, wj = n & 7;
    int pi = p >> 3, pj = p & 7;
    int i = (wi * kP + pi + kSH) & 63;
    int j = (wj * kP + pj + kSH) & 63;
    return (((b << 6) + i) << 6) + j;
}

// ================= tf32 mma.sync GEMM, cp.async 3-stage, BM128 x BN96 =================
#define BN    96
#define ASTR  20
#define BSTR  104          // 96 + 8  (≡8 mod 32 -> conflict-free B-frag LDS)
#define A_STAGE (128*ASTR)     // 2560 floats
#define B_STAGE (16*BSTR)      // 1664 floats
#define GEMM_SMEM ((3*A_STAGE + 3*B_STAGE) * 4)   // 50688 bytes

template<int EPI>
__global__ void __launch_bounds__(128, 2) mma_gemm(
    const float* __restrict__ A, const float* __restrict__ W,
    const float* __restrict__ bias, const float* __restrict__ R,
    float* __restrict__ Co, int M, int N, int K)
{
    extern __shared__ float sm[];
    float* AsB = sm;
    float* BsB = sm + 3 * A_STAGE;

    int tid = threadIdx.x;
    int w = tid >> 5, l = tid & 31;
    int bm = blockIdx.y << 7;
    int bn = blockIdx.x * BN;

    float acc[2][12][4];
    #pragma unroll
    for (int mt = 0; mt < 2; mt++)
        #pragma unroll
        for (int nt = 0; nt < 12; nt++)
            #pragma unroll
            for (int e = 0; e < 4; e++) acc[mt][nt][e] = 0.0f;

    int a_r0 = tid >> 2;            // 0..31
    int a_q  = tid & 3;             // float4 seg in 16-k chunk
    int NC = K >> 4;

    auto issue = [&](int c, int buf) {
        float* As = AsB + buf * A_STAGE;
        float* Bs = BsB + buf * B_STAGE;
        int koff = c * 16;
        #pragma unroll
        for (int j = 0; j < 4; j++)
            cpa16(s2u(&As[(a_r0 + 32*j) * ASTR + a_q * 4]),
                  A + (size_t)(bm + a_r0 + 32*j) * K + koff + a_q * 4);
        // B: 16 rows x 96 cols = 384 float4, 3 per thread
        #pragma unroll
        for (int j = 0; j < 3; j++) {
            int lin = j * 128 + tid;        // 0..383
            int k   = lin / 24;
            int n4  = lin - k * 24;
            cpa16(s2u(&Bs[k * BSTR + n4 * 4]),
                  W + (size_t)(koff + k) * N + bn + n4 * 4);
        }
        cpa_commit();
    };

    issue(0, 0);
    issue(1, 1);

    for (int c = 0; c < NC; c++) {
        cpa_wait<1>();
        __syncthreads();
        if (c + 2 < NC) issue(c + 2, (c + 2) % 3);

        int buf = c % 3;
        const float* As = AsB + buf * A_STAGE;
        const float* Bs = BsB + buf * B_STAGE;
        #pragma unroll
        for (int s = 0; s < 2; s++) {
            int kk = s * 8 + (l & 3);
            uint32_t af[2][4];
            #pragma unroll
            for (int mt = 0; mt < 2; mt++) {
                int m = w * 32 + mt * 16 + (l >> 2);
                af[mt][0] = __float_as_uint(As[m * ASTR + kk]);
                af[mt][1] = __float_as_uint(As[(m + 8) * ASTR + kk]);
                af[mt][2] = __float_as_uint(As[m * ASTR + kk + 4]);
                af[mt][3] = __float_as_uint(As[(m + 8) * ASTR + kk + 4]);
            }
            uint32_t bf[12][2];
            #pragma unroll
            for (int nt = 0; nt < 12; nt++) {
                int n = nt * 8 + (l >> 2);
                bf[nt][0] = __float_as_uint(Bs[kk * BSTR + n]);
                bf[nt][1] = __float_as_uint(Bs[(kk + 4) * BSTR + n]);
            }
            #pragma unroll
            for (int mt = 0; mt < 2; mt++)
                #pragma unroll
                for (int nt = 0; nt < 12; nt++)
                    mma_tf32(acc[mt][nt], af[mt][0], af[mt][1], af[mt][2], af[mt][3],
                             bf[nt][0], bf[nt][1]);
        }
        __syncthreads();
    }

    #pragma unroll
    for (int mt = 0; mt < 2; mt++) {
        int r0 = bm + w * 32 + mt * 16 + (l >> 2);
        int r1 = r0 + 8;
        int o0 = (EPI == 2) ? map_row(r0) : r0;
        int o1 = (EPI == 2) ? map_row(r1) : r1;
        #pragma unroll
        for (int nt = 0; nt < 12; nt++) {
            int col = bn + nt * 8 + ((l & 3) << 1);
            float2 bb = *(const float2*)(bias + col);
            float v0 = acc[mt][nt][0] + bb.x;
            float v1 = acc[mt][nt][1] + bb.y;
            float v2 = acc[mt][nt][2] + bb.x;
            float v3 = acc[mt][nt][3] + bb.y;
            if (EPI == 1) {
                v0 = 0.5f * v0 * (1.0f + erff(v0 * 0.70710678118654752f));
                v1 = 0.5f * v1 * (1.0f + erff(v1 * 0.70710678118654752f));
                v2 = 0.5f * v2 * (1.0f + erff(v2 * 0.70710678118654752f));
                v3 = 0.5f * v3 * (1.0f + erff(v3 * 0.70710678118654752f));
            }
            if (EPI == 2 || EPI == 3) {
                float2 ra = *(const float2*)(R + (size_t)o0 * N + col);
                float2 rb = *(const float2*)(R + (size_t)o1 * N + col);
                v0 += ra.x; v1 += ra.y; v2 += rb.x; v3 += rb.y;
            }
            *(float2*)(Co + (size_t)o0 * N + col) = make_float2(v0, v1);
            *(float2*)(Co + (size_t)o1 * N + col) = make_float2(v2, v3);
        }
    }
}

// ---------------- windowed attention: tf32 mma.sync, smem overlay ----------------
// qs[64][52] and ks[32][72] are dead after QK^T; simp[64][84] overlays them.
// smem pool: 8192 floats = 32 KB.  vs at offset 5632.
__global__ void __launch_bounds__(128) attn_kernel() {
    __shared__ float pool[8192];
    #define QS(r,c)  pool[(r)*52 + (c)]
    #define KSA(d,t) pool[3328 + (d)*72 + (t)]
    #define VSA(r,c) pool[5632 + (r)*40 + (c)]
    #define SP(r,c)  pool[(r)*84 + (c)]

    int tid = threadIdx.x;
    int w = tid >> 5, l = tid & 31;
    int h  = blockIdx.x % kNH;
    int bn = blockIdx.x / kNH;
    int n  = bn & 63;
    size_t rowbase = (size_t)bn * 64;

    // ---- load Q,K,V ----
    #pragma unroll
    for (int it = 0; it < 4; it++) {
        int lin = tid + it * 128;          // 0..511
        int r = lin >> 3;
        int f = (lin & 7) << 2;
        const float* base = &g_qkv[(rowbase + r) * (3 * kC) + h * kHD + f];
        float4 qv = *(const float4*)(base);
        float4 kv = *(const float4*)(base + kC);
        float4 vv = *(const float4*)(base + 2 * kC);
        *(float4*)&QS(r, f) = qv;
        KSA(f + 0, r) = kv.x; KSA(f + 1, r) = kv.y;
        KSA(f + 2, r) = kv.z; KSA(f + 3, r) = kv.w;
        *(float4*)&VSA(r, f) = vv;
    }
    __syncthreads();

    int m0 = w * 16;
    int qr = l >> 2;
    int qc = l & 3;

    // ---- S = Q @ K^T ----
    float acc[8][4];
    #pragma unroll
    for (int nt = 0; nt < 8; nt++)
        #pragma unroll
        for (int e = 0; e < 4; e++) acc[nt][e] = 0.0f;

    #pragma unroll
    for (int s = 0; s < 4; s++) {
        int kk = s * 8 + qc;
        uint32_t a0 = __float_as_uint(QS(m0 + qr, kk));
        uint32_t a1 = __float_as_uint(QS(m0 + 8 + qr, kk));
        uint32_t a2 = __float_as_uint(QS(m0 + qr, kk + 4));
        uint32_t a3 = __float_as_uint(QS(m0 + 8 + qr, kk + 4));
        #pragma unroll
        for (int nt = 0; nt < 8; nt++) {
            int nn = nt * 8 + qr;
            uint32_t b0 = __float_as_uint(KSA(kk, nn));
            uint32_t b1 = __float_as_uint(KSA(kk + 4, nn));
            mma_tf32(acc[nt], a0, a1, a2, a3, b0, b1);
        }
    }

    // ---- scale + rel bias + shift mask (in C-fragment registers) ----
    bool lastRow = (n >> 3) == 7;
    bool lastCol = (n & 7)  == 7;
    const float scale = 0.17677669529663689f;
    int r0 = m0 + qr, r1 = r0 + 8;
    int p0i = r0 >> 3, p0j = r0 & 7;
    int p1i = r1 >> 3, p1j = r1 & 7;

    float mx0 = -1e30f, mx1 = -1e30f;
    #pragma unroll
    for (int nt = 0; nt < 8; nt++) {
        int c0 = nt * 8 + qc * 2;
        float2 bb0 = *(const float2*)&g_btab[h * 4096 + r0 * 64 + c0];
        float2 bb1 = *(const float2*)&g_btab[h * 4096 + r1 * 64 + c0];
        #pragma unroll
        for (int e = 0; e < 2; e++) {
            int q = c0 + e;
            int qi = q >> 3, qj = q & 7;
            float v0 = acc[nt][e]     * scale + (e ? bb0.y : bb0.x);
            float v1 = acc[nt][e + 2] * scale + (e ? bb1.y : bb1.x);
            bool m0b = (lastRow && ((p0i < 4) != (qi < 4))) ||
                       (lastCol && ((p0j < 4) != (qj < 4)));
            bool m1b = (lastRow && ((p1i < 4) != (qi < 4))) ||
                       (lastCol && ((p1j < 4) != (qj < 4)));
            v0 = m0b ? -1e30f : v0;
            v1 = m1b ? -1e30f : v1;
            acc[nt][e]     = v0;
            acc[nt][e + 2] = v1;
            mx0 = fmaxf(mx0, v0);
            mx1 = fmaxf(mx1, v1);
        }
    }
    mx0 = fmaxf(mx0, __shfl_xor_sync(0xffffffffu, mx0, 1));
    mx0 = fmaxf(mx0, __shfl_xor_sync(0xffffffffu, mx0, 2));
    mx1 = fmaxf(mx1, __shfl_xor_sync(0xffffffffu, mx1, 1));
    mx1 = fmaxf(mx1, __shfl_xor_sync(0xffffffffu, mx1, 2));

    float sum0 = 0.0f, sum1 = 0.0f;
    #pragma unroll
    for (int nt = 0; nt < 8; nt++) {
        float e0 = __expf(acc[nt][0] - mx0);
        float e1 = __expf(acc[nt][1] - mx0);
        float e2 = __expf(acc[nt][2] - mx1);
        float e3 = __expf(acc[nt][3] - mx1);
        acc[nt][0] = e0; acc[nt][1] = e1; acc[nt][2] = e2; acc[nt][3] = e3;
        sum0 += e0 + e1;
        sum1 += e2 + e3;
    }
    sum0 += __shfl_xor_sync(0xffffffffu, sum0, 1);
    sum0 += __shfl_xor_sync(0xffffffffu, sum0, 2);
    sum1 += __shfl_xor_sync(0xffffffffu, sum1, 1);
    sum1 += __shfl_xor_sync(0xffffffffu, sum1, 2);
    float inv0 = 1.0f / sum0, inv1 = 1.0f / sum1;

    // ---- write P over the dead Q/K region ----
    __syncthreads();   // all warps done reading qs/ks
    #pragma unroll
    for (int nt = 0; nt < 8; nt++) {
        int c0 = nt * 8 + qc * 2;
        *(float2*)&SP(r0, c0) = make_float2(acc[nt][0] * inv0, acc[nt][1] * inv0);
        *(float2*)&SP(r1, c0) = make_float2(acc[nt][2] * inv1, acc[nt][3] * inv1);
    }
    __syncthreads();

    // ---- O = P @ V ----
    float oacc[4][4];
    #pragma unroll
    for (int nt = 0; nt < 4; nt++)
        #pragma unroll
        for (int e = 0; e < 4; e++) oacc[nt][e] = 0.0f;

    #pragma unroll
    for (int s = 0; s < 8; s++) {
        int kk = s * 8 + qc;
        uint32_t a0 = __float_as_uint(SP(m0 + qr, kk));
        uint32_t a1 = __float_as_uint(SP(m0 + 8 + qr, kk));
        uint32_t a2 = __float_as_uint(SP(m0 + qr, kk + 4));
        uint32_t a3 = __float_as_uint(SP(m0 + 8 + qr, kk + 4));
        #pragma unroll
        for (int nt = 0; nt < 4; nt++) {
            int nn = nt * 8 + qr;
            uint32_t b0 = __float_as_uint(VSA(kk, nn));
            uint32_t b1 = __float_as_uint(VSA(kk + 4, nn));
            mma_tf32(oacc[nt], a0, a1, a2, a3, b0, b1);
        }
    }

    float* d0 = &g_attn[(rowbase + r0) * kC + h * kHD];
    float* d1 = &g_attn[(rowbase + r1) * kC + h * kHD];
    #pragma unroll
    for (int nt = 0; nt < 4; nt++) {
        int c0 = nt * 8 + qc * 2;
        *(float2*)(d0 + c0) = make_float2(oacc[nt][0], oacc[nt][1]);
        *(float2*)(d1 + c0) = make_float2(oacc[nt][2], oacc[nt][3]);
    }
    #undef QS
    #undef KSA
    #undef VSA
    #undef SP
}

// ---------------- launch ----------------
extern "C" void kernel_launch(void* const* d_in, const int* in_sizes, int n_in,
                              void* d_out, int out_size) {
    const float* x      = (const float*)d_in[0];
    const float* g1     = (const float*)d_in[1];
    const float* b1     = (const float*)d_in[2];
    const float* w_qkv  = (const float*)d_in[3];
    const float* b_qkv  = (const float*)d_in[4];
    const float* relp   = (const float*)d_in[5];
    const float* w_proj = (const float*)d_in[6];
    const float* b_proj = (const float*)d_in[7];
    const float* g2     = (const float*)d_in[8];
    const float* b2     = (const float*)d_in[9];
    const float* w_mlp1 = (const float*)d_in[10];
    const float* b_mlp1 = (const float*)d_in[11];
    const float* w_mlp2 = (const float*)d_in[12];
    const float* b_mlp2 = (const float*)d_in[13];
    float* out = (float*)d_out;

    float *hwin, *qkvb, *attnb, *x1, *h2n, *mid;
    cudaGetSymbolAddress((void**)&hwin,  g_hwin);
    cudaGetSymbolAddress((void**)&qkvb,  g_qkv);
    cudaGetSymbolAddress((void**)&attnb, g_attn);
    cudaGetSymbolAddress((void**)&x1,    g_x1);
    cudaGetSymbolAddress((void**)&h2n,   g_h2n);
    cudaGetSymbolAddress((void**)&mid,   g_mid);

    cudaFuncSetAttribute(mma_gemm<0>, cudaFuncAttributeMaxDynamicSharedMemorySize, GEMM_SMEM);
    cudaFuncSetAttribute(mma_gemm<1>, cudaFuncAttributeMaxDynamicSharedMemorySize, GEMM_SMEM);
    cudaFuncSetAttribute(mma_gemm<2>, cudaFuncAttributeMaxDynamicSharedMemorySize, GEMM_SMEM);
    cudaFuncSetAttribute(mma_gemm<3>, cudaFuncAttributeMaxDynamicSharedMemorySize, GEMM_SMEM);

    // 1. relative-position bias table
    btab_kernel<<<(kNH * kPP * kPP + 255) / 256, 256>>>(relp);
    // 2. LN1 + roll + window partition
    ln1_kernel<<<kTOK, kC>>>(x, g1, b1);
    // 3. QKV GEMM: [65536,192] @ [192,576]
    mma_gemm<0><<<dim3(576 / BN, kTOK / 128), 128, GEMM_SMEM>>>(
        hwin, w_qkv, b_qkv, nullptr, qkvb, kTOK, 576, kC);
    // 4. windowed attention (tensorized)
    attn_kernel<<<kB * kNW * kNH, 128>>>();
    // 5. proj GEMM + window-reverse + roll-back + residual
    mma_gemm<2><<<dim3(kC / BN, kTOK / 128), 128, GEMM_SMEM>>>(
        attnb, w_proj, b_proj, x, x1, kTOK, kC, kC);
    // 6. LN2
    ln2_kernel<<<kTOK, kC>>>(g2, b2);
    // 7. MLP1 + GELU
    mma_gemm<1><<<dim3(768 / BN, kTOK / 128), 128, GEMM_SMEM>>>(
        h2n, w_mlp1, b_mlp1, nullptr, mid, kTOK, 768, kC);
    // 8. MLP2 + residual -> out
    mma_gemm<3><<<dim3(kC / BN, kTOK / 128), 128, GEMM_SMEM>>>(
        mid, w_mlp2, b_mlp2, x1, out, kTOK, kC, 768);
}